// round 2
// baseline (speedup 1.0000x reference)
#include <cuda_runtime.h>
#include <cstdint>

#define Bb 256
#define Ss 512
#define Ff 64
#define Hh 128
#define BSF (Bb*Ss*Ff)

typedef unsigned long long u64;

// ---------------- device scratch (no runtime alloc allowed) ----------------
__device__ __align__(16) float g_Wg[131072];   // k-pair-interleaved [Wih|Whh]^T, 512KB
__device__ float g_dinv[Ss];
__device__ float g_lossbuf[64];

// ---------------- helpers ----------------
__device__ __forceinline__ u64 f2fma(u64 a, u64 b, u64 c){
    u64 d;
    asm("fma.rn.f32x2 %0, %1, %2, %3;" : "=l"(d) : "l"(a), "l"(b), "l"(c));
    return d;
}
__device__ __forceinline__ float flo(u64 v){ return __uint_as_float((unsigned)v); }
__device__ __forceinline__ float fhi(u64 v){ return __uint_as_float((unsigned)(v>>32)); }
__device__ __forceinline__ float sigf(float v){ return __fdividef(1.f, 1.f + __expf(-v)); }
__device__ __forceinline__ float tanhf_(float v){ return __fdividef(2.f, 1.f + __expf(-2.f*v)) - 1.f; }

// ---------------- prep: gates weight transpose + k-pair interleave ----------------
// g_Wg[kp*1024 + j*2 + e] = Wcat[j][2*kp+e],  Wcat = [Wih | Whh] along K (K=256)
__global__ void k_prep(const float* __restrict__ Wih, const float* __restrict__ Whh){
    int id  = blockIdx.x * 256 + threadIdx.x;   // 512 blocks
    int kp  = id >> 10;
    int rem = id & 1023;
    int j   = rem >> 1;
    int e   = rem & 1;
    int k   = (kp << 1) | e;
    g_Wg[id] = (k < 128) ? Wih[(j << 7) + k] : Whh[(j << 7) + (k - 128)];
}

// ---------------- prep: per-step 1/denom ----------------
__global__ void k_denoms(const float* __restrict__ m){
    __shared__ float red[256];
    int l = blockIdx.x, t = threadIdx.x;
    int f = t & 63, rb = t >> 6;
    float s = 0.f;
    for (int b = rb; b < Bb; b += 4)
        s += m[(((b << 9) + l) << 6) + f];
    red[t] = s; __syncthreads();
    for (int o = 128; o > 0; o >>= 1){ if (t < o) red[t] += red[t + o]; __syncthreads(); }
    if (t == 0) g_dinv[l] = 1.0f / (red[0] + 1e-5f);
}

// ---------------- smem layout (float offsets) ----------------
#define OFF_WDH   0        // [128][68]
#define OFF_WTR   8704     // [64][132]
#define OFF_WFR   17152    // [64][68]  (diag zeroed)
#define OFF_WWC   21504    // [64][132]
#define OFF_DWDM  29952    // [64]
#define OFF_BDH   30016    // [128]
#define OFF_BDM   30144    // [64]
#define OFF_BTR   30208
#define OFF_BFR   30272
#define OFF_BWC   30336
#define OFF_BIHH  30400    // [512] bih+bhh
#define OFF_DINV  30912    // [512]
#define OFF_A     31424    // [4][256] : [0:64)=cl_c  [64:128)=ml  [128:256)=h
#define OFF_TL    32448    // [4][64]
#define OFF_GM    32704    // [4][64]
#define OFF_XC    32960    // [4][64]
#define OFF_G     33216    // [4][512] activated gates
#define OFF_RED   35264    // [256]
#define SMEM_FLOATS 35520
#define SMEM_BYTES  (SMEM_FLOATS * 4)

// ---------------- main persistent recurrence ----------------
__global__ void __launch_bounds__(256, 1)
k_main(const float* __restrict__ x, const float* __restrict__ m, const float* __restrict__ tt,
       const float* __restrict__ Wdh, const float* __restrict__ bdh,
       const float* __restrict__ Wdm, const float* __restrict__ bdm,
       const float* __restrict__ Wtr, const float* __restrict__ btr,
       const float* __restrict__ Wfr, const float* __restrict__ bfr,
       const float* __restrict__ Wwc, const float* __restrict__ bwc,
       const float* __restrict__ bih, const float* __restrict__ bhh,
       float* __restrict__ out)
{
    extern __shared__ float sm[];
    const int t  = threadIdx.x;
    const int b0 = blockIdx.x << 2;

    // ---- one-time smem fills ----
    for (int i = t; i < 128*64; i += 256) sm[OFF_WDH + (i>>6)*68  + (i&63)]  = Wdh[i];
    for (int i = t; i < 64*128; i += 256) sm[OFF_WTR + (i>>7)*132 + (i&127)] = Wtr[i];
    for (int i = t; i < 64*64;  i += 256){ int r = i>>6, c = i&63;
        sm[OFF_WFR + r*68 + c] = (r == c) ? 0.f : Wfr[i]; }
    for (int i = t; i < 64*128; i += 256) sm[OFF_WWC + (i>>7)*132 + (i&127)] = Wwc[i];
    if (t < 64){
        sm[OFF_DWDM + t] = Wdm[t*64 + t];
        sm[OFF_BDM + t] = bdm[t]; sm[OFF_BTR + t] = btr[t];
        sm[OFF_BFR + t] = bfr[t]; sm[OFF_BWC + t] = bwc[t];
    }
    if (t < 128) sm[OFF_BDH + t] = bdh[t];
    for (int i = t; i < 512; i += 256){
        sm[OFF_BIHH + i] = bih[i] + bhh[i];
        sm[OFF_DINV + i] = g_dinv[i];
    }

    const int f_ = t & 63,  r_ = t >> 6;    // elementwise map (row, feature)
    const int jh = t & 127, rh = t >> 7;    // H map: rows {rh, rh+2}
    const int gt = t >> 6;                  // gate type of cols {2t,2t+1}

    // zero h state
    sm[OFF_A + rh*256       + 128 + jh] = 0.f;
    sm[OFF_A + (rh+2)*256   + 128 + jh] = 0.f;

    const int inb = ((b0 + r_) << 15) + f_;       // (b0+r_)*S*F + f_
    float xlv = x[inb], mlv = m[inb], tlv = tt[inb];
    sm[OFF_TL + (r_<<6) + f_] = tlv;
    sm[OFF_A + (r_<<8) + 64 + f_] = mlv;
    __syncthreads();

    float c0 = 0.f, c1 = 0.f, lacc = 0.f;
    float xln, mln, tln;
    const float* __restrict__ wgf = g_Wg + (t << 2);

    #pragma unroll 1
    for (int l = 0; l < Ss; ++l){
        const float dinv = sm[OFF_DINV + l];
        const float dm   = mlv * dinv;

        // ===== gamma_h (jh map, row pair shares weight reads) + gamma_m (r_ map) =====
        {
            const float* wr = sm + OFF_WDH + jh*68;
            const float* ta = sm + OFF_TL + (rh << 6);
            const float* tb = sm + OFF_TL + ((rh+2) << 6);
            float a0 = sm[OFF_BDH + jh], a1 = a0;
            #pragma unroll
            for (int q = 0; q < 16; ++q){
                float4 w = *(const float4*)(wr + (q<<2));
                float4 u = *(const float4*)(ta + (q<<2));
                float4 v = *(const float4*)(tb + (q<<2));
                a0 = fmaf(w.x,u.x, fmaf(w.y,u.y, fmaf(w.z,u.z, fmaf(w.w,u.w, a0))));
                a1 = fmaf(w.x,v.x, fmaf(w.y,v.y, fmaf(w.z,v.z, fmaf(w.w,v.w, a1))));
            }
            float gh0 = __expf(-fmaxf(a0, 0.f));
            float gh1 = __expf(-fmaxf(a1, 0.f));
            sm[OFF_A + rh*256     + 128 + jh] *= gh0;
            sm[OFF_A + (rh+2)*256 + 128 + jh] *= gh1;
            float gm = __expf(-fmaxf(fmaf(tlv, sm[OFF_DWDM + f_], sm[OFF_BDM + f_]), 0.f));
            sm[OFF_GM + (r_<<6) + f_] = gm;
        }
        __syncthreads();

        // ===== xl_hat = h @ Wtr^T + btr   (r_ map) =====
        float xh;
        {
            const float* wr = sm + OFF_WTR + f_*132;
            const float* hr = sm + OFF_A + (r_<<8) + 128;
            float a = sm[OFF_BTR + f_];
            #pragma unroll 8
            for (int q = 0; q < 32; ++q){
                float4 w  = *(const float4*)(wr + (q<<2));
                float4 h4 = *(const float4*)(hr + (q<<2));
                a = fmaf(w.x,h4.x, fmaf(w.y,h4.y, fmaf(w.z,h4.z, fmaf(w.w,h4.w, a))));
            }
            xh = a;
            float d = xlv - xh;
            lacc = fmaf(d*d, dm, lacc);
            float xc = fmaf(mlv, d, xh);           // ml*xl + (1-ml)*xh
            sm[OFF_XC + (r_<<6) + f_] = xc;
        }
        __syncthreads();

        // ===== zl_hat, beta, cl_hat, imputation + loss (r_ map) =====
        {
            const float* wr = sm + OFF_WFR + f_*68;
            const float* xr = sm + OFF_XC + (r_<<6);
            float z = sm[OFF_BFR + f_];
            #pragma unroll
            for (int q = 0; q < 16; ++q){
                float4 w = *(const float4*)(wr + (q<<2));
                float4 u = *(const float4*)(xr + (q<<2));
                z = fmaf(w.x,u.x, fmaf(w.y,u.y, fmaf(w.z,u.z, fmaf(w.w,u.w, z))));
            }
            const float* wc = sm + OFF_WWC + f_*132;
            const float* gr = sm + OFF_GM + (r_<<6);
            const float* mr = sm + OFF_A + (r_<<8) + 64;
            float bt = sm[OFF_BWC + f_];
            #pragma unroll
            for (int q = 0; q < 16; ++q){
                float4 w = *(const float4*)(wc + (q<<2));
                float4 u = *(const float4*)(gr + (q<<2));
                bt = fmaf(w.x,u.x, fmaf(w.y,u.y, fmaf(w.z,u.z, fmaf(w.w,u.w, bt))));
            }
            #pragma unroll
            for (int q = 0; q < 16; ++q){
                float4 w = *(const float4*)(wc + 64 + (q<<2));
                float4 u = *(const float4*)(mr + (q<<2));
                bt = fmaf(w.x,u.x, fmaf(w.y,u.y, fmaf(w.z,u.z, fmaf(w.w,u.w, bt))));
            }
            float d2 = xlv - z;
            lacc = fmaf(d2*d2, dm, lacc);
            float ch = fmaf(bt, z - xh, xh);       // beta*z + (1-beta)*xh
            float d3 = xlv - ch;
            lacc = fmaf(d3*d3, dm, lacc);
            float clc = fmaf(mlv, d3, ch);         // ml*xl + (1-ml)*ch
            out[inb + (l << 6)] = clc;
            sm[OFF_A + (r_<<8) + f_] = clc;
        }
        __syncthreads();

        // ===== gates GEMM: cols {2t,2t+1} x 4 rows, K=256, f32x2 over k-pairs =====
        {
            int ln = (l < Ss-1) ? (l + 1) : l;     // prefetch next-step inputs under GEMM
            xln = x[inb + (ln << 6)];
            mln = m[inb + (ln << 6)];
            tln = tt[inb + (ln << 6)];

            u64 P[4] = {0,0,0,0}, Q[4] = {0,0,0,0};
            const float* a0p = sm + OFF_A;
            #pragma unroll 4
            for (int kp2 = 0; kp2 < 64; ++kp2){
                ulonglong2 w0 = *(const ulonglong2*)(wgf + (kp2 << 11));
                ulonglong2 w1 = *(const ulonglong2*)(wgf + (kp2 << 11) + 1024);
                ulonglong2 a0 = *(const ulonglong2*)(a0p +       (kp2 << 2));
                ulonglong2 a1 = *(const ulonglong2*)(a0p + 256 + (kp2 << 2));
                ulonglong2 a2 = *(const ulonglong2*)(a0p + 512 + (kp2 << 2));
                ulonglong2 a3 = *(const ulonglong2*)(a0p + 768 + (kp2 << 2));
                P[0]=f2fma(w0.x,a0.x,P[0]); Q[0]=f2fma(w0.y,a0.x,Q[0]);
                P[0]=f2fma(w1.x,a0.y,P[0]); Q[0]=f2fma(w1.y,a0.y,Q[0]);
                P[1]=f2fma(w0.x,a1.x,P[1]); Q[1]=f2fma(w0.y,a1.x,Q[1]);
                P[1]=f2fma(w1.x,a1.y,P[1]); Q[1]=f2fma(w1.y,a1.y,Q[1]);
                P[2]=f2fma(w0.x,a2.x,P[2]); Q[2]=f2fma(w0.y,a2.x,Q[2]);
                P[2]=f2fma(w1.x,a2.y,P[2]); Q[2]=f2fma(w1.y,a2.y,Q[2]);
                P[3]=f2fma(w0.x,a3.x,P[3]); Q[3]=f2fma(w0.y,a3.x,Q[3]);
                P[3]=f2fma(w1.x,a3.y,P[3]); Q[3]=f2fma(w1.y,a3.y,Q[3]);
            }
            float b0f = sm[OFF_BIHH + (t<<1)];
            float b1f = sm[OFF_BIHH + (t<<1) + 1];
            #pragma unroll
            for (int r = 0; r < 4; ++r){
                float v0 = flo(P[r]) + fhi(P[r]) + b0f;
                float v1 = flo(Q[r]) + fhi(Q[r]) + b1f;
                if (gt == 2){ v0 = tanhf_(v0); v1 = tanhf_(v1); }   // g gate
                else        { v0 = sigf(v0);   v1 = sigf(v1);   }   // i,f,o gates
                *(float2*)(sm + OFF_G + (r << 9) + (t << 1)) = make_float2(v0, v1);
            }
        }
        __syncthreads();

        // ===== LSTM combine (jh map, c in regs) + stage next-step inputs =====
        {
            const float* gA = sm + OFF_G + rh*512;
            const float* gB = sm + OFF_G + (rh+2)*512;
            float i0 = gA[jh], fg0 = gA[128+jh], gg0 = gA[256+jh], o0 = gA[384+jh];
            c0 = fmaf(fg0, c0, i0*gg0);
            sm[OFF_A + rh*256 + 128 + jh] = o0 * tanhf_(c0);
            float i1 = gB[jh], fg1 = gB[128+jh], gg1 = gB[256+jh], o1 = gB[384+jh];
            c1 = fmaf(fg1, c1, i1*gg1);
            sm[OFF_A + (rh+2)*256 + 128 + jh] = o1 * tanhf_(c1);

            sm[OFF_TL + (r_<<6) + f_] = tln;
            sm[OFF_A + (r_<<8) + 64 + f_] = mln;
            xlv = xln; mlv = mln; tlv = tln;
        }
        __syncthreads();
    }

    // ---- deterministic loss reduction ----
    sm[OFF_RED + t] = lacc; __syncthreads();
    for (int o = 128; o > 0; o >>= 1){ if (t < o) sm[OFF_RED+t] += sm[OFF_RED+t+o]; __syncthreads(); }
    if (t == 0) g_lossbuf[blockIdx.x] = sm[OFF_RED];
}

__global__ void k_final(float* __restrict__ out){
    float s = 0.f;
    for (int i = 0; i < 64; ++i) s += g_lossbuf[i];   // fixed order: deterministic
    out[BSF] = s * (1.0f / (float)Ss);
}

// ---------------- launcher ----------------
extern "C" void kernel_launch(void* const* d_in, const int* in_sizes, int n_in,
                              void* d_out, int out_size) {
    const float* x   = (const float*)d_in[0];
    const float* m   = (const float*)d_in[1];
    const float* tt  = (const float*)d_in[2];
    const float* Wdh = (const float*)d_in[3];
    const float* bdh = (const float*)d_in[4];
    const float* Wdm = (const float*)d_in[5];
    const float* bdm = (const float*)d_in[6];
    const float* Wtr = (const float*)d_in[7];
    const float* btr = (const float*)d_in[8];
    const float* Wfr = (const float*)d_in[9];
    const float* bfr = (const float*)d_in[10];
    const float* Wwc = (const float*)d_in[11];
    const float* bwc = (const float*)d_in[12];
    const float* Wih = (const float*)d_in[13];
    const float* Whh = (const float*)d_in[14];
    const float* bih = (const float*)d_in[15];
    const float* bhh = (const float*)d_in[16];
    float* out = (float*)d_out;

    cudaFuncSetAttribute(k_main, cudaFuncAttributeMaxDynamicSharedMemorySize, SMEM_BYTES);

    k_prep<<<512, 256>>>(Wih, Whh);
    k_denoms<<<512, 256>>>(m);
    k_main<<<64, 256, SMEM_BYTES>>>(x, m, tt, Wdh, bdh, Wdm, bdm, Wtr, btr,
                                    Wfr, bfr, Wwc, bwc, bih, bhh, out);
    if (out_size > BSF) k_final<<<1, 1>>>(out);
}

// round 3
// speedup vs baseline: 1.1042x; 1.1042x over previous
#include <cuda_runtime.h>
#include <cstdint>

#define Bb 256
#define Ss 512
#define Ff 64
#define Hh 128
#define BSF (Bb*Ss*Ff)
#define NCTA 64
#define KPSM 9          // k-pair-quads cached in smem (of 64)

typedef unsigned long long u64;

// ---------------- device scratch (no runtime alloc) ----------------
__device__ __align__(16) float g_Wg[131072];   // k-pair-interleaved [Wih|Whh]^T
__device__ float g_dinv[Ss];
__device__ float g_lossbuf[NCTA];
__device__ int   g_ctr = 0;

// ---------------- helpers ----------------
__device__ __forceinline__ u64 f2fma(u64 a, u64 b, u64 c){
    u64 d;
    asm("fma.rn.f32x2 %0, %1, %2, %3;" : "=l"(d) : "l"(a), "l"(b), "l"(c));
    return d;
}
__device__ __forceinline__ float flo(u64 v){ return __uint_as_float((unsigned)v); }
__device__ __forceinline__ float fhi(u64 v){ return __uint_as_float((unsigned)(v>>32)); }
__device__ __forceinline__ float sigf(float v){ return __fdividef(1.f, 1.f + __expf(-v)); }
__device__ __forceinline__ float tanhf_(float v){ return __fdividef(2.f, 1.f + __expf(-2.f*v)) - 1.f; }

// ---------------- prep: weight transpose (blocks 0..511) + denoms (512..1023) ----------------
__global__ void k_prep(const float* __restrict__ Wih, const float* __restrict__ Whh,
                       const float* __restrict__ m){
    int bid = blockIdx.x, t = threadIdx.x;
    if (bid < 512){
        int id  = bid * 256 + t;
        int kp  = id >> 10;
        int rem = id & 1023;
        int j   = rem >> 1;
        int e   = rem & 1;
        int k   = (kp << 1) | e;
        g_Wg[id] = (k < 128) ? Wih[(j << 7) + k] : Whh[(j << 7) + (k - 128)];
    } else {
        __shared__ float red[256];
        int l = bid - 512;
        int f = t & 63, rb = t >> 6;
        float s = 0.f;
        for (int b = rb; b < Bb; b += 4)
            s += m[(((b << 9) + l) << 6) + f];
        red[t] = s; __syncthreads();
        for (int o = 128; o > 0; o >>= 1){ if (t < o) red[t] += red[t + o]; __syncthreads(); }
        if (t == 0) g_dinv[l] = 1.0f / (red[0] + 1e-5f);
        if (l == 0 && t == 0) g_ctr = 0;
    }
}

// ---------------- smem layout (float offsets) ----------------
#define OFF_WDH   0        // [128][68]
#define OFF_WTR   8704     // [64][132]
#define OFF_WFR   17152    // [64][68]  (diag zeroed)
#define OFF_WWC   21504    // [64][132]
#define OFF_DWDM  29952    // [64]
#define OFF_BDH   30016    // [128]
#define OFF_BDM   30144    // [64]
#define OFF_BTR   30208
#define OFF_BFR   30272
#define OFF_BWC   30336
#define OFF_BIHH  30400    // [512]
#define OFF_DINV  30912    // [512]
#define OFF_A     31424    // [4][264] : [0:64)=cl_c [64:128)=ml [128:256)=h, pad 8
#define OFF_TL    32480    // [4][72]
#define OFF_GM    32768    // [4][72]
#define OFF_XC    33056    // [4][72]
#define OFF_XL    33344    // [4][72]
#define OFF_G     33632    // [4][512]
#define OFF_RED   35680    // [256]
#define OFF_WG    35936    // [KPSM*2048] cached gates weights
#define SMEM_FLOATS (35936 + KPSM*2048)
#define SMEM_BYTES  (SMEM_FLOATS * 4)

// ---------------- main persistent recurrence ----------------
__global__ void __launch_bounds__(256, 1)
k_main(const float* __restrict__ x, const float* __restrict__ m, const float* __restrict__ tt,
       const float* __restrict__ Wdh, const float* __restrict__ bdh,
       const float* __restrict__ Wdm, const float* __restrict__ bdm,
       const float* __restrict__ Wtr, const float* __restrict__ btr,
       const float* __restrict__ Wfr, const float* __restrict__ bfr,
       const float* __restrict__ Wwc, const float* __restrict__ bwc,
       const float* __restrict__ bih, const float* __restrict__ bhh,
       float* __restrict__ out, int wloss)
{
    extern __shared__ float sm[];
    const int t  = threadIdx.x;
    const int b0 = blockIdx.x << 2;

    // ---- one-time smem fills ----
    for (int i = t; i < 128*64; i += 256) sm[OFF_WDH + (i>>6)*68  + (i&63)]  = Wdh[i];
    for (int i = t; i < 64*128; i += 256) sm[OFF_WTR + (i>>7)*132 + (i&127)] = Wtr[i];
    for (int i = t; i < 64*64;  i += 256){ int r = i>>6, c = i&63;
        sm[OFF_WFR + r*68 + c] = (r == c) ? 0.f : Wfr[i]; }
    for (int i = t; i < 64*128; i += 256) sm[OFF_WWC + (i>>7)*132 + (i&127)] = Wwc[i];
    if (t < 64){
        sm[OFF_DWDM + t] = Wdm[t*64 + t];
        sm[OFF_BDM + t] = bdm[t]; sm[OFF_BTR + t] = btr[t];
        sm[OFF_BFR + t] = bfr[t]; sm[OFF_BWC + t] = bwc[t];
    }
    if (t < 128) sm[OFF_BDH + t] = bdh[t];
    for (int i = t; i < 512; i += 256){
        sm[OFF_BIHH + i] = bih[i] + bhh[i];
        sm[OFF_DINV + i] = g_dinv[i];
    }
    for (int i = t; i < KPSM*2048; i += 256) sm[OFF_WG + i] = g_Wg[i];
    // zero h
    for (int i = t; i < 512; i += 256){
        int r = i >> 7, j = i & 127;
        sm[OFF_A + r*264 + 128 + j] = 0.f;
    }

    // thread maps
    const int fl = t & 63,  rl = t >> 6;     // global-load map (coalesced)
    const int fe = t >> 2,  re = t & 3;      // elementwise/output map (broadcast weights)
    const int jg = t >> 1,  rg = t & 1;      // gamma_h map: rows {rg, rg+2}
    const int jh = t & 127, rh = t >> 7;     // LSTM map: rows {rh, rh+2}
    const int gt = t >> 6;                   // gate type of cols {2t,2t+1}

    const int inb = ((b0 + rl) << 15) + fl;
    { // stage step 0 inputs
        float xv = x[inb], mv = m[inb], tv = tt[inb];
        sm[OFF_XL + rl*72 + fl] = xv;
        sm[OFF_TL + rl*72 + fl] = tv;
        sm[OFF_A  + rl*264 + 64 + fl] = mv;
    }
    __syncthreads();

    float c0 = 0.f, c1 = 0.f, lacc = 0.f;
    float xn, mn, tn;
    const float* __restrict__ wgf = g_Wg + (t << 2);
    const int tx4 = t << 2;

    #pragma unroll 1
    for (int l = 0; l < Ss; ++l){
        const float dinv = sm[OFF_DINV + l];

        // ===== A: gamma_h (jg map, weight rows broadcast x2) + gamma_m (fe,re) =====
        {
            const float* wr = sm + OFF_WDH + jg*68;
            const float* ta = sm + OFF_TL + rg*72;
            const float* tb = sm + OFF_TL + (rg+2)*72;
            float a0=0.f,a1=0.f,b0a=0.f,b1a=0.f;
            #pragma unroll
            for (int q = 0; q < 16; ++q){
                float4 w = *(const float4*)(wr + (q<<2));
                float4 u = *(const float4*)(ta + (q<<2));
                float4 v = *(const float4*)(tb + (q<<2));
                a0  = fmaf(w.x,u.x, fmaf(w.y,u.y, a0));
                a1  = fmaf(w.z,u.z, fmaf(w.w,u.w, a1));
                b0a = fmaf(w.x,v.x, fmaf(w.y,v.y, b0a));
                b1a = fmaf(w.z,v.z, fmaf(w.w,v.w, b1a));
            }
            float bb = sm[OFF_BDH + jg];
            float gh0 = __expf(-fmaxf(a0 + a1 + bb, 0.f));
            float gh1 = __expf(-fmaxf(b0a + b1a + bb, 0.f));
            sm[OFF_A + rg*264     + 128 + jg] *= gh0;
            sm[OFF_A + (rg+2)*264 + 128 + jg] *= gh1;

            float tl_ = sm[OFF_TL + re*72 + fe];
            float gm = __expf(-fmaxf(fmaf(tl_, sm[OFF_DWDM + fe], sm[OFF_BDM + fe]), 0.f));
            sm[OFF_GM + re*72 + fe] = gm;
        }
        __syncthreads();

        // ===== B: xl_hat (fe,re map; weight rows broadcast x4) =====
        float xh, xlv, mlv, dmv;
        {
            const float* wr = sm + OFF_WTR + fe*132;
            const float* hr = sm + OFF_A + re*264 + 128;
            float s0=0.f,s1=0.f,s2=0.f,s3=0.f;
            #pragma unroll
            for (int q = 0; q < 32; q += 2){
                float4 w  = *(const float4*)(wr + (q<<2));
                float4 h4 = *(const float4*)(hr + (q<<2));
                s0 = fmaf(w.x,h4.x, fmaf(w.y,h4.y, s0));
                s1 = fmaf(w.z,h4.z, fmaf(w.w,h4.w, s1));
                w  = *(const float4*)(wr + ((q+1)<<2));
                h4 = *(const float4*)(hr + ((q+1)<<2));
                s2 = fmaf(w.x,h4.x, fmaf(w.y,h4.y, s2));
                s3 = fmaf(w.z,h4.z, fmaf(w.w,h4.w, s3));
            }
            xh  = s0 + s1 + s2 + s3 + sm[OFF_BTR + fe];
            xlv = sm[OFF_XL + re*72 + fe];
            mlv = sm[OFF_A + re*264 + 64 + fe];
            dmv = mlv * dinv;
            float d = xlv - xh;
            lacc = fmaf(d*d, dmv, lacc);
            sm[OFF_XC + re*72 + fe] = fmaf(mlv, d, xh);
        }
        __syncthreads();

        // ===== C: z, beta, cl_hat, cl_c, loss (fe,re map) =====
        {
            const float* wr = sm + OFF_WFR + fe*68;
            const float* xr = sm + OFF_XC + re*72;
            float z0=0.f,z1=0.f;
            #pragma unroll
            for (int q = 0; q < 16; ++q){
                float4 w = *(const float4*)(wr + (q<<2));
                float4 u = *(const float4*)(xr + (q<<2));
                z0 = fmaf(w.x,u.x, fmaf(w.y,u.y, z0));
                z1 = fmaf(w.z,u.z, fmaf(w.w,u.w, z1));
            }
            float z = z0 + z1 + sm[OFF_BFR + fe];

            const float* wc = sm + OFF_WWC + fe*132;
            const float* gr = sm + OFF_GM + re*72;
            const float* mr = sm + OFF_A + re*264 + 64;
            float t0=0.f,t1=0.f;
            #pragma unroll
            for (int q = 0; q < 16; ++q){
                float4 w = *(const float4*)(wc + (q<<2));
                float4 u = *(const float4*)(gr + (q<<2));
                t0 = fmaf(w.x,u.x, fmaf(w.y,u.y, t0));
                t1 = fmaf(w.z,u.z, fmaf(w.w,u.w, t1));
            }
            #pragma unroll
            for (int q = 0; q < 16; ++q){
                float4 w = *(const float4*)(wc + 64 + (q<<2));
                float4 u = *(const float4*)(mr + (q<<2));
                t0 = fmaf(w.x,u.x, fmaf(w.y,u.y, t0));
                t1 = fmaf(w.z,u.z, fmaf(w.w,u.w, t1));
            }
            float bt = t0 + t1 + sm[OFF_BWC + fe];

            float d2 = xlv - z;
            lacc = fmaf(d2*d2, dmv, lacc);
            float ch = fmaf(bt, z - xh, xh);
            float d3 = xlv - ch;
            lacc = fmaf(d3*d3, dmv, lacc);
            sm[OFF_A + re*264 + fe] = fmaf(mlv, d3, ch);   // cl_c
        }
        __syncthreads();

        // ===== D: gates GEMM + prefetch next inputs + store imputation =====
        {
            int ln = (l < Ss-1) ? (l + 1) : l;
            xn = x[inb + (ln << 6)];
            mn = m[inb + (ln << 6)];
            tn = tt[inb + (ln << 6)];
            out[inb + (l << 6)] = sm[OFF_A + rl*264 + fl];   // coalesced cl_c store

            u64 P0[4]={0,0,0,0}, P1[4]={0,0,0,0}, Q0[4]={0,0,0,0}, Q1[4]={0,0,0,0};
            const float* a0p = sm + OFF_A;

            #pragma unroll 3
            for (int kp2 = 0; kp2 < KPSM; ++kp2){
                const float* wp = sm + OFF_WG + (kp2 << 11) + tx4;
                ulonglong2 w0 = *(const ulonglong2*)wp;
                ulonglong2 w1 = *(const ulonglong2*)(wp + 1024);
                ulonglong2 a0 = *(const ulonglong2*)(a0p +       (kp2 << 2));
                ulonglong2 a1 = *(const ulonglong2*)(a0p + 264 + (kp2 << 2));
                ulonglong2 a2 = *(const ulonglong2*)(a0p + 528 + (kp2 << 2));
                ulonglong2 a3 = *(const ulonglong2*)(a0p + 792 + (kp2 << 2));
                P0[0]=f2fma(w0.x,a0.x,P0[0]); Q0[0]=f2fma(w0.y,a0.x,Q0[0]);
                P1[0]=f2fma(w1.x,a0.y,P1[0]); Q1[0]=f2fma(w1.y,a0.y,Q1[0]);
                P0[1]=f2fma(w0.x,a1.x,P0[1]); Q0[1]=f2fma(w0.y,a1.x,Q0[1]);
                P1[1]=f2fma(w1.x,a1.y,P1[1]); Q1[1]=f2fma(w1.y,a1.y,Q1[1]);
                P0[2]=f2fma(w0.x,a2.x,P0[2]); Q0[2]=f2fma(w0.y,a2.x,Q0[2]);
                P1[2]=f2fma(w1.x,a2.y,P1[2]); Q1[2]=f2fma(w1.y,a2.y,Q1[2]);
                P0[3]=f2fma(w0.x,a3.x,P0[3]); Q0[3]=f2fma(w0.y,a3.x,Q0[3]);
                P1[3]=f2fma(w1.x,a3.y,P1[3]); Q1[3]=f2fma(w1.y,a3.y,Q1[3]);
            }
            #pragma unroll 8
            for (int kp2 = KPSM; kp2 < 64; ++kp2){
                ulonglong2 w0 = *(const ulonglong2*)(wgf + (kp2 << 11));
                ulonglong2 w1 = *(const ulonglong2*)(wgf + (kp2 << 11) + 1024);
                ulonglong2 a0 = *(const ulonglong2*)(a0p +       (kp2 << 2));
                ulonglong2 a1 = *(const ulonglong2*)(a0p + 264 + (kp2 << 2));
                ulonglong2 a2 = *(const ulonglong2*)(a0p + 528 + (kp2 << 2));
                ulonglong2 a3 = *(const ulonglong2*)(a0p + 792 + (kp2 << 2));
                P0[0]=f2fma(w0.x,a0.x,P0[0]); Q0[0]=f2fma(w0.y,a0.x,Q0[0]);
                P1[0]=f2fma(w1.x,a0.y,P1[0]); Q1[0]=f2fma(w1.y,a0.y,Q1[0]);
                P0[1]=f2fma(w0.x,a1.x,P0[1]); Q0[1]=f2fma(w0.y,a1.x,Q0[1]);
                P1[1]=f2fma(w1.x,a1.y,P1[1]); Q1[1]=f2fma(w1.y,a1.y,Q1[1]);
                P0[2]=f2fma(w0.x,a2.x,P0[2]); Q0[2]=f2fma(w0.y,a2.x,Q0[2]);
                P1[2]=f2fma(w1.x,a2.y,P1[2]); Q1[2]=f2fma(w1.y,a2.y,Q1[2]);
                P0[3]=f2fma(w0.x,a3.x,P0[3]); Q0[3]=f2fma(w0.y,a3.x,Q0[3]);
                P1[3]=f2fma(w1.x,a3.y,P1[3]); Q1[3]=f2fma(w1.y,a3.y,Q1[3]);
            }
            float b0f = sm[OFF_BIHH + (t<<1)];
            float b1f = sm[OFF_BIHH + (t<<1) + 1];
            #pragma unroll
            for (int r = 0; r < 4; ++r){
                float v0 = (flo(P0[r]) + fhi(P0[r])) + (flo(P1[r]) + fhi(P1[r])) + b0f;
                float v1 = (flo(Q0[r]) + fhi(Q0[r])) + (flo(Q1[r]) + fhi(Q1[r])) + b1f;
                if (gt == 2){ v0 = tanhf_(v0); v1 = tanhf_(v1); }
                else        { v0 = sigf(v0);   v1 = sigf(v1);   }
                *(float2*)(sm + OFF_G + (r << 9) + (t << 1)) = make_float2(v0, v1);
            }
        }
        __syncthreads();

        // ===== E: LSTM combine (jh map) + stage next inputs =====
        {
            const float* gA = sm + OFF_G + rh*512;
            const float* gB = sm + OFF_G + (rh+2)*512;
            float i0 = gA[jh], fg0 = gA[128+jh], gg0 = gA[256+jh], o0 = gA[384+jh];
            c0 = fmaf(fg0, c0, i0*gg0);
            sm[OFF_A + rh*264 + 128 + jh] = o0 * tanhf_(c0);
            float i1 = gB[jh], fg1 = gB[128+jh], gg1 = gB[256+jh], o1 = gB[384+jh];
            c1 = fmaf(fg1, c1, i1*gg1);
            sm[OFF_A + (rh+2)*264 + 128 + jh] = o1 * tanhf_(c1);

            sm[OFF_XL + rl*72 + fl] = xn;
            sm[OFF_TL + rl*72 + fl] = tn;
            sm[OFF_A  + rl*264 + 64 + fl] = mn;
        }
        __syncthreads();
    }

    // ---- loss reduction + inter-CTA finish (all 64 CTAs co-resident) ----
    sm[OFF_RED + t] = lacc; __syncthreads();
    for (int o = 128; o > 0; o >>= 1){ if (t < o) sm[OFF_RED+t] += sm[OFF_RED+t+o]; __syncthreads(); }
    if (t == 0){
        g_lossbuf[blockIdx.x] = sm[OFF_RED];
        __threadfence();
        atomicAdd(&g_ctr, 1);
        if (blockIdx.x == 0){
            while (atomicAdd(&g_ctr, 0) < NCTA) { }
            float s = 0.f;
            #pragma unroll 1
            for (int i = 0; i < NCTA; ++i) s += ((volatile float*)g_lossbuf)[i];
            if (wloss) out[BSF] = s * (1.0f / (float)Ss);
            g_ctr = 0;
        }
    }
}

// ---------------- launcher ----------------
extern "C" void kernel_launch(void* const* d_in, const int* in_sizes, int n_in,
                              void* d_out, int out_size) {
    const float* x   = (const float*)d_in[0];
    const float* m   = (const float*)d_in[1];
    const float* tt  = (const float*)d_in[2];
    const float* Wdh = (const float*)d_in[3];
    const float* bdh = (const float*)d_in[4];
    const float* Wdm = (const float*)d_in[5];
    const float* bdm = (const float*)d_in[6];
    const float* Wtr = (const float*)d_in[7];
    const float* btr = (const float*)d_in[8];
    const float* Wfr = (const float*)d_in[9];
    const float* bfr = (const float*)d_in[10];
    const float* Wwc = (const float*)d_in[11];
    const float* bwc = (const float*)d_in[12];
    const float* Wih = (const float*)d_in[13];
    const float* Whh = (const float*)d_in[14];
    const float* bih = (const float*)d_in[15];
    const float* bhh = (const float*)d_in[16];
    float* out = (float*)d_out;

    cudaFuncSetAttribute(k_main, cudaFuncAttributeMaxDynamicSharedMemorySize, SMEM_BYTES);

    k_prep<<<1024, 256>>>(Wih, Whh, m);
    k_main<<<NCTA, 256, SMEM_BYTES>>>(x, m, tt, Wdh, bdh, Wdm, bdm, Wtr, btr,
                                      Wfr, bfr, Wwc, bwc, bih, bhh, out,
                                      (out_size > BSF) ? 1 : 0);
}